// round 4
// baseline (speedup 1.0000x reference)
#include <cuda_runtime.h>
#include <cuda_bf16.h>
#include <math.h>

#define N_NODES 100000
#define N_EDGES 20000
#define N_INC   800000
#define D_IN    256
#define D_HID   16
#define D_OUT   40
#define PAD_E   128     // max edge degree bucket (mean 40)
#define PAD_V   64      // max node degree bucket (mean 8)

// ---------------- scratch (device globals) ----------------
__device__ float g_XW1[(size_t)N_NODES * D_HID];   // H @ W1
__device__ float g_e1 [(size_t)N_EDGES * D_HID];   // e_feat layer1 (normalized)
__device__ float g_XW2[(size_t)N_NODES * D_OUT];   // relu-feat @ W2
__device__ float g_e2 [(size_t)N_EDGES * D_OUT];   // e_feat layer2 (normalized)
__device__ int   g_cnt_e[N_EDGES];
__device__ int   g_cnt_v[N_NODES];
__device__ int   g_buf_e[(size_t)N_EDGES * PAD_E]; // member node indices per edge
__device__ int   g_buf_v[(size_t)N_NODES * PAD_V]; // incident edge indices per node

// ---------------- zero counters ----------------
#define ZC ((N_EDGES + N_NODES) / 4)
__global__ void zero_cnt_kernel() {
    int i = blockIdx.x * blockDim.x + threadIdx.x;
    if (i >= ZC) return;
    int4 z = make_int4(0, 0, 0, 0);
    if (i < N_EDGES / 4) reinterpret_cast<int4*>(g_cnt_e)[i] = z;
    else reinterpret_cast<int4*>(g_cnt_v)[i - N_EDGES / 4] = z;
}

// ---------------- build padded buckets ----------------
__global__ void fill_kernel(const int* __restrict__ ni, const int* __restrict__ ei) {
    int i = blockIdx.x * blockDim.x + threadIdx.x;
    if (i >= N_INC) return;
    int v = __ldg(&ni[i]);
    int e = __ldg(&ei[i]);
    int se = atomicAdd(&g_cnt_e[e], 1);
    if (se < PAD_E) g_buf_e[(size_t)e * PAD_E + se] = v;
    int sv = atomicAdd(&g_cnt_v[v], 1);
    if (sv < PAD_V) g_buf_v[(size_t)v * PAD_V + sv] = e;
}

// ---------------- GEMM1: XW1 = H @ W1  (100000x256 @ 256x16) ----------------
__global__ void gemm1_kernel(const float* __restrict__ H, const float* __restrict__ W1) {
    __shared__ float sW[D_IN * D_HID];
    for (int i = threadIdx.x; i < D_IN * D_HID; i += blockDim.x) sW[i] = W1[i];
    __syncthreads();

    int row = blockIdx.x * blockDim.x + threadIdx.x;
    if (row >= N_NODES) return;

    float acc[D_HID];
#pragma unroll
    for (int j = 0; j < D_HID; j++) acc[j] = 0.f;

    const float4* hp = reinterpret_cast<const float4*>(H + (size_t)row * D_IN);
#pragma unroll 4
    for (int k4 = 0; k4 < D_IN / 4; k4++) {
        float4 hv = hp[k4];
        const float* wr = &sW[k4 * 4 * D_HID];
        float xs[4] = {hv.x, hv.y, hv.z, hv.w};
#pragma unroll
        for (int c = 0; c < 4; c++) {
            const float4* w4 = reinterpret_cast<const float4*>(wr + c * D_HID);
            float4 wa = w4[0], wb = w4[1], wc = w4[2], wd = w4[3];
            float x = xs[c];
            acc[0]  += x * wa.x;  acc[1]  += x * wa.y;  acc[2]  += x * wa.z;  acc[3]  += x * wa.w;
            acc[4]  += x * wb.x;  acc[5]  += x * wb.y;  acc[6]  += x * wb.z;  acc[7]  += x * wb.w;
            acc[8]  += x * wc.x;  acc[9]  += x * wc.y;  acc[10] += x * wc.z;  acc[11] += x * wc.w;
            acc[12] += x * wd.x;  acc[13] += x * wd.y;  acc[14] += x * wd.z;  acc[15] += x * wd.w;
        }
    }
    float4* op = reinterpret_cast<float4*>(g_XW1 + (size_t)row * D_HID);
    op[0] = make_float4(acc[0],  acc[1],  acc[2],  acc[3]);
    op[1] = make_float4(acc[4],  acc[5],  acc[6],  acc[7]);
    op[2] = make_float4(acc[8],  acc[9],  acc[10], acc[11]);
    op[3] = make_float4(acc[12], acc[13], acc[14], acc[15]);
}

// ---------------- edge gather 1: e1[e] = (Σ w_v XW1[v]) / max(Σ w_v,1e-6) ----
// warp/edge; half-warp per member stream; 4 members in flight per half-warp
__global__ void edge_gather1_kernel(const float* __restrict__ w) {
    int warp = (blockIdx.x * blockDim.x + threadIdx.x) >> 5;
    int lane = threadIdx.x & 31;
    if (warp >= N_EDGES) return;
    int e = warp;
    int cnt = min(__ldg(&g_cnt_e[e]), PAD_E);
    int half = lane >> 4, fl = lane & 15;

    const int* buf = g_buf_e + (size_t)e * PAD_E;
    float a0 = 0.f, a1 = 0.f, a2 = 0.f, a3 = 0.f;
    float s0 = 0.f, s1 = 0.f, s2 = 0.f, s3 = 0.f;
    int m = half;
    for (; m + 6 < cnt; m += 8) {
        int v0 = __ldg(&buf[m]),     v1 = __ldg(&buf[m + 2]);
        int v2 = __ldg(&buf[m + 4]), v3 = __ldg(&buf[m + 6]);
        float w0 = __ldg(&w[v0]), w1 = __ldg(&w[v1]);
        float w2 = __ldg(&w[v2]), w3 = __ldg(&w[v3]);
        float x0 = __ldg(&g_XW1[(size_t)v0 * D_HID + fl]);
        float x1 = __ldg(&g_XW1[(size_t)v1 * D_HID + fl]);
        float x2 = __ldg(&g_XW1[(size_t)v2 * D_HID + fl]);
        float x3 = __ldg(&g_XW1[(size_t)v3 * D_HID + fl]);
        a0 += w0 * x0; s0 += w0;
        a1 += w1 * x1; s1 += w1;
        a2 += w2 * x2; s2 += w2;
        a3 += w3 * x3; s3 += w3;
    }
    for (; m < cnt; m += 2) {
        int v0 = __ldg(&buf[m]);
        float w0 = __ldg(&w[v0]);
        a0 += w0 * __ldg(&g_XW1[(size_t)v0 * D_HID + fl]);
        s0 += w0;
    }
    float acc  = (a0 + a1) + (a2 + a3);
    float wsum = (s0 + s1) + (s2 + s3);
    acc  += __shfl_xor_sync(0xFFFFFFFFu, acc, 16);
    wsum += __shfl_xor_sync(0xFFFFFFFFu, wsum, 16);
    float inv = __frcp_rn(fmaxf(wsum, 1e-6f));
    if (lane < D_HID) g_e1[(size_t)e * D_HID + lane] = acc * inv;
}

// ---------------- node gather 1 fused with relu + GEMM2 ----------------------
__global__ void node_gather1_gemm2_kernel(const float* __restrict__ W2,
                                          const float* __restrict__ b1) {
    __shared__ float sW[D_HID * D_OUT];
    __shared__ float sB[D_HID];
    for (int i = threadIdx.x; i < D_HID * D_OUT; i += blockDim.x) sW[i] = W2[i];
    if (threadIdx.x < D_HID) sB[threadIdx.x] = b1[threadIdx.x];
    __syncthreads();

    int warp = (blockIdx.x * blockDim.x + threadIdx.x) >> 5;
    int lane = threadIdx.x & 31;
    if (warp >= N_NODES) return;
    int v = warp;
    int cnt = min(__ldg(&g_cnt_v[v]), PAD_V);
    int half = lane >> 4, fl = lane & 15;

    const int* buf = g_buf_v + (size_t)v * PAD_V;
    float a0 = 0.f, a1 = 0.f, a2 = 0.f, a3 = 0.f;
    int m = half;
    for (; m + 6 < cnt; m += 8) {
        int e0 = __ldg(&buf[m]),     e1 = __ldg(&buf[m + 2]);
        int e2 = __ldg(&buf[m + 4]), e3 = __ldg(&buf[m + 6]);
        a0 += __ldg(&g_e1[(size_t)e0 * D_HID + fl]);
        a1 += __ldg(&g_e1[(size_t)e1 * D_HID + fl]);
        a2 += __ldg(&g_e1[(size_t)e2 * D_HID + fl]);
        a3 += __ldg(&g_e1[(size_t)e3 * D_HID + fl]);
    }
    for (; m < cnt; m += 2) {
        int e0 = __ldg(&buf[m]);
        a0 += __ldg(&g_e1[(size_t)e0 * D_HID + fl]);
    }
    float acc = (a0 + a1) + (a2 + a3);
    acc += __shfl_xor_sync(0xFFFFFFFFu, acc, 16);

    float invd = __frcp_rn(fmaxf((float)cnt, 1.f));
    float x = fmaxf(acc * invd + sB[fl], 0.f);   // lane holds x[fl] (dup across halves)

    float o0 = 0.f, o1 = 0.f;
#pragma unroll
    for (int k = 0; k < D_HID; k++) {
        float xk = __shfl_sync(0xFFFFFFFFu, x, k);
        o0 += xk * sW[k * D_OUT + lane];
        if (lane < D_OUT - 32) o1 += xk * sW[k * D_OUT + 32 + lane];
    }
    g_XW2[(size_t)v * D_OUT + lane] = o0;
    if (lane < D_OUT - 32) g_XW2[(size_t)v * D_OUT + 32 + lane] = o1;
}

// ---------------- edge gather 2: warp/edge, float2 lanes (20 active), 4-deep --
__global__ void edge_gather2_kernel(const float* __restrict__ w) {
    int warp = (blockIdx.x * blockDim.x + threadIdx.x) >> 5;
    int lane = threadIdx.x & 31;
    if (warp >= N_EDGES) return;
    int e = warp;
    int cnt = min(__ldg(&g_cnt_e[e]), PAD_E);
    bool act = lane < D_OUT / 2;   // 20 lanes, one float2 each

    const int* buf = g_buf_e + (size_t)e * PAD_E;
    float2 a0 = {0.f, 0.f}, a1 = {0.f, 0.f}, a2 = {0.f, 0.f}, a3 = {0.f, 0.f};
    float wsum = 0.f;
    int m = 0;
    for (; m + 3 < cnt; m += 4) {
        int v0 = __ldg(&buf[m]),     v1 = __ldg(&buf[m + 1]);
        int v2 = __ldg(&buf[m + 2]), v3 = __ldg(&buf[m + 3]);
        float w0 = __ldg(&w[v0]), w1 = __ldg(&w[v1]);
        float w2 = __ldg(&w[v2]), w3 = __ldg(&w[v3]);
        wsum += (w0 + w1) + (w2 + w3);
        if (act) {
            float2 x0 = __ldg(reinterpret_cast<const float2*>(g_XW2 + (size_t)v0 * D_OUT) + lane);
            float2 x1 = __ldg(reinterpret_cast<const float2*>(g_XW2 + (size_t)v1 * D_OUT) + lane);
            float2 x2 = __ldg(reinterpret_cast<const float2*>(g_XW2 + (size_t)v2 * D_OUT) + lane);
            float2 x3 = __ldg(reinterpret_cast<const float2*>(g_XW2 + (size_t)v3 * D_OUT) + lane);
            a0.x += w0 * x0.x; a0.y += w0 * x0.y;
            a1.x += w1 * x1.x; a1.y += w1 * x1.y;
            a2.x += w2 * x2.x; a2.y += w2 * x2.y;
            a3.x += w3 * x3.x; a3.y += w3 * x3.y;
        }
    }
    for (; m < cnt; m++) {
        int v0 = __ldg(&buf[m]);
        float w0 = __ldg(&w[v0]);
        wsum += w0;
        if (act) {
            float2 x0 = __ldg(reinterpret_cast<const float2*>(g_XW2 + (size_t)v0 * D_OUT) + lane);
            a0.x += w0 * x0.x; a0.y += w0 * x0.y;
        }
    }
    float inv = __frcp_rn(fmaxf(wsum, 1e-6f));
    if (act) {
        float2 r;
        r.x = ((a0.x + a1.x) + (a2.x + a3.x)) * inv;
        r.y = ((a0.y + a1.y) + (a2.y + a3.y)) * inv;
        reinterpret_cast<float2*>(g_e2 + (size_t)e * D_OUT)[lane] = r;
    }
}

// ---------------- node gather 2 fused with bias + log_softmax ----------------
__global__ void node_gather2_fin_kernel(float* __restrict__ out,
                                        const float* __restrict__ b2) {
    int warp = (blockIdx.x * blockDim.x + threadIdx.x) >> 5;
    int lane = threadIdx.x & 31;
    if (warp >= N_NODES) return;
    int v = warp;
    int cnt = min(__ldg(&g_cnt_v[v]), PAD_V);
    bool act = lane < D_OUT / 2;

    const int* buf = g_buf_v + (size_t)v * PAD_V;
    float2 a0 = {0.f, 0.f}, a1 = {0.f, 0.f}, a2 = {0.f, 0.f}, a3 = {0.f, 0.f};
    int m = 0;
    for (; m + 3 < cnt; m += 4) {
        int e0 = __ldg(&buf[m]),     e1 = __ldg(&buf[m + 1]);
        int e2 = __ldg(&buf[m + 2]), e3 = __ldg(&buf[m + 3]);
        if (act) {
            float2 x0 = __ldg(reinterpret_cast<const float2*>(g_e2 + (size_t)e0 * D_OUT) + lane);
            float2 x1 = __ldg(reinterpret_cast<const float2*>(g_e2 + (size_t)e1 * D_OUT) + lane);
            float2 x2 = __ldg(reinterpret_cast<const float2*>(g_e2 + (size_t)e2 * D_OUT) + lane);
            float2 x3 = __ldg(reinterpret_cast<const float2*>(g_e2 + (size_t)e3 * D_OUT) + lane);
            a0.x += x0.x; a0.y += x0.y;
            a1.x += x1.x; a1.y += x1.y;
            a2.x += x2.x; a2.y += x2.y;
            a3.x += x3.x; a3.y += x3.y;
        }
    }
    for (; m < cnt; m++) {
        int e0 = __ldg(&buf[m]);
        if (act) {
            float2 x0 = __ldg(reinterpret_cast<const float2*>(g_e2 + (size_t)e0 * D_OUT) + lane);
            a0.x += x0.x; a0.y += x0.y;
        }
    }
    float invd = __frcp_rn(fmaxf((float)cnt, 1.f));
    float2 val = {-INFINITY, -INFINITY};
    if (act) {
        float2 bb = __ldg(reinterpret_cast<const float2*>(b2) + lane);
        val.x = ((a0.x + a1.x) + (a2.x + a3.x)) * invd + bb.x;
        val.y = ((a0.y + a1.y) + (a2.y + a3.y)) * invd + bb.y;
    }

    float mx = fmaxf(val.x, val.y);
#pragma unroll
    for (int off = 16; off > 0; off >>= 1)
        mx = fmaxf(mx, __shfl_xor_sync(0xFFFFFFFFu, mx, off));

    float s = act ? (__expf(val.x - mx) + __expf(val.y - mx)) : 0.f;
#pragma unroll
    for (int off = 16; off > 0; off >>= 1)
        s += __shfl_xor_sync(0xFFFFFFFFu, s, off);

    float lse = mx + __logf(s);
    if (act) {
        float2 r = {val.x - lse, val.y - lse};
        reinterpret_cast<float2*>(out + (size_t)v * D_OUT)[lane] = r;
    }
}

// ---------------- launch ----------------
extern "C" void kernel_launch(void* const* d_in, const int* in_sizes, int n_in,
                              void* d_out, int out_size) {
    const float* H   = (const float*)d_in[0];
    const float* w   = (const float*)d_in[1];
    const int*   ni  = (const int*)  d_in[2];
    const int*   ei  = (const int*)  d_in[3];
    const float* W1  = (const float*)d_in[4];
    const float* b1  = (const float*)d_in[5];
    const float* W2  = (const float*)d_in[6];
    const float* b2  = (const float*)d_in[7];
    float*       out = (float*)d_out;

    const int T = 256;
    auto blocks = [](long n, int t) { return (int)((n + t - 1) / t); };

    zero_cnt_kernel<<<blocks(ZC, T), T>>>();
    fill_kernel<<<blocks(N_INC, T), T>>>(ni, ei);
    gemm1_kernel<<<blocks(N_NODES, T), T>>>(H, W1);

    edge_gather1_kernel<<<blocks((long)N_EDGES * 32, T), T>>>(w);
    node_gather1_gemm2_kernel<<<blocks((long)N_NODES * 32, T), T>>>(W2, b1);

    edge_gather2_kernel<<<blocks((long)N_EDGES * 32, T), T>>>(w);
    node_gather2_fin_kernel<<<blocks((long)N_NODES * 32, T), T>>>(out, b2);
}